// round 16
// baseline (speedup 1.0000x reference)
#include <cuda_runtime.h>
#include <math.h>

// Problem constants
#define BB 32
#define LL 64
#define EE 512
#define DH 1024
#define G4 4096
#define VV 32000
#define MAXBLK 148
#define NTILES_OP 125   // 32000 / 256
#define NT 512          // persistent-kernel block size

typedef unsigned long long ull;

// ---------------- scratch (device globals; no allocation allowed) ----------
__device__ __align__(16) float g_Xenc[LL * BB * G4];      // embed@enc_wx + enc_b
__device__ __align__(16) float g_enc_outs[BB * LL * DH];  // encoder hidden states
__device__ __align__(16) float g_part[8 * BB * G4];       // gates/enc split-K partials
__device__ __align__(16) float g_part2[8 * BB * DH];      // comb split-K partials
__device__ __align__(16) float g_h[BB * DH];
__device__ __align__(16) float g_c[BB * DH];
__device__ __align__(16) float g_e[BB * DH];
__device__ __align__(16) float g_ctx[BB * DH];
__device__ float g_pm[BB][128];   // per-outproj-tile max
__device__ float g_ps[BB][128];   // per-outproj-tile sum exp(x - tilemax)
__device__ int   g_pi[BB][128];   // per-outproj-tile argmax
__device__ float g_lse[BB][LL];   // log-sum-exp per (b, t), subtracted in epilogue

// grid barrier state (flag per block + generation; monotonic across replays)
__device__ volatile unsigned g_flags[MAXBLK];
__device__ volatile unsigned g_gen2;

// ---------------- f32x2 helpers (sm_103a packed FMA) -----------------------
__device__ __forceinline__ ull pk2(float w) {
    ull r; asm("mov.b64 %0, {%1, %1};" : "=l"(r) : "f"(w)); return r;
}
__device__ __forceinline__ void fma2(ull& d, ull a, ull b) {
    asm("fma.rn.f32x2 %0, %1, %2, %0;" : "+l"(d) : "l"(a), "l"(b));
}
__device__ __forceinline__ float2 upk(ull v) {
    float2 f; asm("mov.b64 {%0, %1}, %2;" : "=f"(f.x), "=f"(f.y) : "l"(v)); return f;
}
__device__ __forceinline__ float sigm(float x) { return 1.0f / (1.0f + expf(-x)); }

// ---------------- device-wide barrier: flag array + leader -----------------
__device__ __forceinline__ void gsync() {
    __threadfence();               // release
    __syncthreads();
    int tid = threadIdx.x, bx = blockIdx.x, nb = gridDim.x;
    if (bx == 0) {
        unsigned target = g_gen2 + 1;
        if (tid == 0) g_flags[0] = target;
        if (tid > 0 && tid < nb)
            while ((int)(g_flags[tid] - target) < 0) __nanosleep(32);
        __syncthreads();
        if (tid == 0) { __threadfence(); g_gen2 = target; }
    } else {
        if (tid == 0) {
            unsigned target = g_gen2 + 1;
            g_flags[bx] = target;
            while ((int)(g_gen2 - target) < 0) __nanosleep(32);
            __threadfence();       // acquire (CCTL.IVALL -> fresh L1)
        }
    }
    __syncthreads();
}

// ---------------- one-time: Xenc[t] = embed(x[:,t]) @ enc_wx + enc_b -------
__global__ __launch_bounds__(256) void k_enc_pre(
    const int* __restrict__ x, const float* __restrict__ emb,
    const float* __restrict__ wx, const float* __restrict__ bias)
{
    __shared__ __align__(16) float As[32][34];
    int tid = threadIdx.x;
    int t = blockIdx.z;
    int txq = tid & 31, ty = tid >> 5;
    int c0 = blockIdx.x * 128 + txq * 4;
    int lb = tid >> 3, lk = (tid & 7) * 4;
    int tok = x[lb * LL + t];
    const float* arow = emb + (size_t)tok * EE;

    ull acc[4][2];
#pragma unroll
    for (int j = 0; j < 4; j++) { acc[j][0] = 0; acc[j][1] = 0; }

    for (int kc = 0; kc < EE; kc += 32) {
        __syncthreads();
        float4 v = *(const float4*)(arow + kc + lk);
        As[lk + 0][lb] = v.x; As[lk + 1][lb] = v.y;
        As[lk + 2][lb] = v.z; As[lk + 3][lb] = v.w;
        __syncthreads();
#pragma unroll 8
        for (int kk = 0; kk < 32; kk++) {
            float4 w4 = *(const float4*)(wx + (size_t)(kc + kk) * G4 + c0);
            ull wp0 = pk2(w4.x), wp1 = pk2(w4.y), wp2 = pk2(w4.z), wp3 = pk2(w4.w);
            ull a0 = *(const ull*)&As[kk][ty * 4];
            ull a1 = *(const ull*)&As[kk][ty * 4 + 2];
            fma2(acc[0][0], a0, wp0); fma2(acc[0][1], a1, wp0);
            fma2(acc[1][0], a0, wp1); fma2(acc[1][1], a1, wp1);
            fma2(acc[2][0], a0, wp2); fma2(acc[2][1], a1, wp2);
            fma2(acc[3][0], a0, wp3); fma2(acc[3][1], a1, wp3);
        }
    }
    float4 bv = *(const float4*)(bias + c0);
    float bj[4] = {bv.x, bv.y, bv.z, bv.w};
    float* outt = g_Xenc + (size_t)t * BB * G4;
#pragma unroll
    for (int j = 0; j < 4; j++) {
        int c = c0 + j;
#pragma unroll
        for (int rp = 0; rp < 2; rp++) {
            float2 v = upk(acc[j][rp]);
            int row = ty * 4 + rp * 2;
            outt[row * G4 + c]       = v.x + bj[j];
            outt[(row + 1) * G4 + c] = v.y + bj[j];
        }
    }
}

// fused A-loader for the gates GEMM: reduce 8 comb partials + bias + relu
__device__ __forceinline__ float4 comb_fetch(
    const float* __restrict__ combb, int row, int d)
{
    float4 s = *(const float4*)(combb + d);
    const float* base = g_part2 + (size_t)row * DH + d;
#pragma unroll
    for (int sp = 0; sp < 8; sp++) {
        float4 p = *(const float4*)(base + (size_t)sp * (BB * DH));
        s.x += p.x; s.y += p.y; s.z += p.z; s.w += p.w;
    }
    s.x = fmaxf(s.x, 0.f); s.y = fmaxf(s.y, 0.f);
    s.z = fmaxf(s.z, 0.f); s.w = fmaxf(s.w, 0.f);
    return s;
}

// ============ 256-col x 32-row GEMM core, KSTEP=16, 512 threads ============
// 16 warps own 16-col ranges; within warp 4 col-lanes x 8 row-lanes.
// Thread = 4 cols (2 f32x2 col-pairs) x 4 rows -> 8 FMA2 per kk.
// Per kk per warp: 1 LDS.128 (W) + 2 LDS.128 (A) + 8 FMA2.
// Ws: float[2][16][256] (32KB). Au: ull[2][16][34] (pad 34 -> 272B rows,
// keeps all [kk][rl*4] ulonglong2 loads 16B aligned).
#define G256_LOOP(ACCBODY)                                                    \
    float (*Ws)[16][256] = (float(*)[16][256])SM;                             \
    ull   (*Au)[16][34]  = (ull(*)[16][34])(SM + 32768);                      \
    int tid = threadIdx.x;                                                    \
    int lane = tid & 31, wrp = tid >> 5;                                      \
    int cl = lane & 3, rl = lane >> 2;                                        \
    int wcol = wrp * 16 + cl * 4;                                             \
    int wr = tid >> 6, wf = tid & 63;                                         \
    int ab = tid >> 2, aq = (tid & 3) * 4;                                    \
    (void)ab; (void)aq;                                                       \
    float4 wld0, wld1; float4 av = make_float4(0.f, 0.f, 0.f, 0.f);           \
    wld0 = LDW(Wb + (size_t)wr * ldW + cb + wf * 4);                          \
    wld1 = LDW(Wb + (size_t)(wr + 8) * ldW + cb + wf * 4);                    \
    if (tid < 128) av = LDA(0);                                               \
    ull acc[2][4];                                                            \
    _Pragma("unroll")                                                         \
    for (int cp = 0; cp < 2; cp++)                                            \
        _Pragma("unroll")                                                     \
        for (int r = 0; r < 4; r++) acc[cp][r] = 0;                           \
    int buf = 0;                                                              \
    for (int kc = 0; kc < KC; kc += 16) {                                     \
        *(float4*)&Ws[buf][wr][wf * 4]     = wld0;                            \
        *(float4*)&Ws[buf][wr + 8][wf * 4] = wld1;                            \
        if (tid < 128) {                                                      \
            Au[buf][aq + 0][ab] = pk2(av.x);                                  \
            Au[buf][aq + 1][ab] = pk2(av.y);                                  \
            Au[buf][aq + 2][ab] = pk2(av.z);                                  \
            Au[buf][aq + 3][ab] = pk2(av.w);                                  \
        }                                                                     \
        __syncthreads();                                                      \
        if (kc + 16 < KC) {                                                   \
            const float* wn = Wb + (size_t)(kc + 16) * ldW;                   \
            wld0 = LDW(wn + (size_t)wr * ldW + cb + wf * 4);                  \
            wld1 = LDW(wn + (size_t)(wr + 8) * ldW + cb + wf * 4);            \
            if (tid < 128) av = LDA(kc + 16);                                 \
        }                                                                     \
        _Pragma("unroll")                                                     \
        for (int kk = 0; kk < 16; kk++) {                                     \
            ulonglong2 wA = *(const ulonglong2*)&Ws[buf][kk][wcol];           \
            ulonglong2 aA = *(const ulonglong2*)&Au[buf][kk][rl * 4];         \
            ulonglong2 aB = *(const ulonglong2*)&Au[buf][kk][rl * 4 + 2];     \
            fma2(acc[0][0], wA.x, aA.x); fma2(acc[0][1], wA.x, aA.y);         \
            fma2(acc[0][2], wA.x, aB.x); fma2(acc[0][3], wA.x, aB.y);         \
            fma2(acc[1][0], wA.y, aA.x); fma2(acc[1][1], wA.y, aA.y);         \
            fma2(acc[1][2], wA.y, aB.x); fma2(acc[1][3], wA.y, aB.y);         \
        }                                                                     \
        buf ^= 1;                                                             \
    }                                                                         \
    __syncthreads();                                                          \
    ACCBODY
// acc[cp][r] = cols (cb+wcol+2cp, +1) x row (rl*4 + r)

#define WRITE_PARTIALS                                                        \
    {                                                                         \
        _Pragma("unroll")                                                     \
        for (int r = 0; r < 4; r++) {                                         \
            int row = rl * 4 + r;                                             \
            _Pragma("unroll")                                                 \
            for (int cp = 0; cp < 2; cp++) {                                  \
                float2 v = upk(acc[cp][r]);                                   \
                *(float2*)&outp[(size_t)row * Nout + cb + wcol + 2 * cp] = v; \
            }                                                                 \
        }                                                                     \
    }

// plain A (row-major, stride DH): encoder / gates-h
__device__ __forceinline__ void gemm256(
    const float* __restrict__ Ab, const float* __restrict__ Wb,
    int ldW, int KC, float* __restrict__ outp, int Nout, int cb, char* SM)
{
#define LDW(p) (*(const float4*)(p))
#define LDA(off) (*(const float4*)(Ab + ab * DH + (off) + aq))
    G256_LOOP(WRITE_PARTIALS)
#undef LDA
#undef LDW
}

// A = relu(comb partial-sum + comb_b) computed inline (gates gemm, k0 < DH)
__device__ __forceinline__ void gemm256_comb(
    int d0, const float* __restrict__ combb, const float* __restrict__ Wb,
    int ldW, int KC, float* __restrict__ outp, int Nout, int cb, char* SM)
{
#define LDW(p) (*(const float4*)(p))
#define LDA(off) comb_fetch(combb, ab, d0 + (off) + aq)
    G256_LOOP(WRITE_PARTIALS)
#undef LDA
#undef LDW
}

// outproj variant: streams out_w, adds bias, writes raw logits + per-tile
// max/argmax/expsum stats (quad shfl + 16-warp smem merge).
__device__ __forceinline__ void outproj256(
    const float* __restrict__ Ab, const float* __restrict__ Wb,
    int ldW, int KC, const float* __restrict__ bias,
    float* __restrict__ out, int t, int tile, int cb, char* SM)
{
#define LDW(p) __ldcs((const float4*)(p))
#define LDA(off) (*(const float4*)(Ab + ab * DH + (off) + aq))
    G256_LOOP({
        float* smax = (float*)SM;                 // [32][16]
        float* ssum = smax + 512;                 // [32][16]
        int*   sidx = (int*)(ssum + 512);         // [32][16]
        float2 bv[2];
#pragma unroll
        for (int cp = 0; cp < 2; cp++)
            bv[cp] = *(const float2*)&bias[cb + wcol + 2 * cp];
#pragma unroll
        for (int r = 0; r < 4; r++) {
            int row = rl * 4 + r;
            float v[4];
#pragma unroll
            for (int cp = 0; cp < 2; cp++) {
                float2 x = upk(acc[cp][r]);
                v[cp * 2]     = x.x + bv[cp].x;
                v[cp * 2 + 1] = x.y + bv[cp].y;
            }
            float* orow = out + ((size_t)(row * LL + t)) * VV + cb + wcol;
#pragma unroll
            for (int cp = 0; cp < 2; cp++)
                *(float2*)&orow[cp * 2] = make_float2(v[cp * 2], v[cp * 2 + 1]);
            float m = v[0]; int mi = cb + wcol;
#pragma unroll
            for (int cc = 1; cc < 4; cc++)
                if (v[cc] > m) { m = v[cc]; mi = cb + wcol + cc; }
#pragma unroll
            for (int o = 1; o <= 2; o <<= 1) {
                float om = __shfl_xor_sync(0xFFFFFFFFu, m, o);
                int   oi = __shfl_xor_sync(0xFFFFFFFFu, mi, o);
                if (om > m || (om == m && oi < mi)) { m = om; mi = oi; }
            }
            float s = 0.f;
#pragma unroll
            for (int cc = 0; cc < 4; cc++) s += __expf(v[cc] - m);
#pragma unroll
            for (int o = 1; o <= 2; o <<= 1)
                s += __shfl_xor_sync(0xFFFFFFFFu, s, o);
            if (cl == 0) {
                smax[row * 16 + wrp] = m;
                ssum[row * 16 + wrp] = s;
                sidx[row * 16 + wrp] = mi;
            }
        }
        __syncthreads();
        if (tid < 32) {
            int row = tid;
            float M = smax[row * 16]; int I = sidx[row * 16];
#pragma unroll
            for (int w2 = 1; w2 < 16; w2++) {
                float om = smax[row * 16 + w2];
                if (om > M) { M = om; I = sidx[row * 16 + w2]; }  // asc cols
            }
            float S = 0.f;
#pragma unroll
            for (int w2 = 0; w2 < 16; w2++)
                S += ssum[row * 16 + w2] * __expf(smax[row * 16 + w2] - M);
            g_pm[row][tile] = M;
            g_ps[row][tile] = S;
            g_pi[row][tile] = I;
        }
        __syncthreads();
    })
#undef LDA
#undef LDW
}

// ---------------- 64-col GEMM core (comb), 512 threads, KSTEP=32 -----------
// Thread = 1 col-pair x 2 rows -> 2 FMA2/kk.
__device__ __forceinline__ void gemm64(
    const float* __restrict__ Ab, const float* __restrict__ Wb,
    int ldW, int KC, float* __restrict__ outp, int Nout, int cb, char* SM)
{
    float (*Ws)[32][64] = (float(*)[32][64])SM;
    ull   (*Au)[32][34] = (ull(*)[32][34])(SM + 16384);
    int tid = threadIdx.x;
    int cg = tid & 31, tr = tid >> 5;            // colpair 0..31, rowpair 0..15
    int wr0 = tid >> 4, wc0 = (tid & 15) * 4;    // W: 1 float4/thread (32x16)
    int lb = tid >> 3, lk = (tid & 7) * 4;       // A: tid<256

    float4 w0 = *(const float4*)(Wb + (size_t)wr0 * ldW + cb + wc0);
    float4 av = make_float4(0.f, 0.f, 0.f, 0.f);
    if (tid < 256) av = *(const float4*)(Ab + lb * DH + lk);

    ull acc0 = 0, acc1 = 0;
    int buf = 0;
    for (int kc = 0; kc < KC; kc += 32) {
        *(float4*)&Ws[buf][wr0][wc0] = w0;
        if (tid < 256) {
            Au[buf][lk + 0][lb] = pk2(av.x);
            Au[buf][lk + 1][lb] = pk2(av.y);
            Au[buf][lk + 2][lb] = pk2(av.z);
            Au[buf][lk + 3][lb] = pk2(av.w);
        }
        __syncthreads();
        if (kc + 32 < KC) {
            const float* wp = Wb + (size_t)(kc + 32) * ldW;
            w0 = *(const float4*)(wp + (size_t)wr0 * ldW + cb + wc0);
            if (tid < 256) av = *(const float4*)(Ab + lb * DH + kc + 32 + lk);
        }
#pragma unroll
        for (int kk = 0; kk < 32; kk++) {
            ull wv = *(const ull*)&Ws[buf][kk][cg * 2];
            ulonglong2 a2 = *(const ulonglong2*)&Au[buf][kk][tr * 2];
            fma2(acc0, wv, a2.x);
            fma2(acc1, wv, a2.y);
        }
        buf ^= 1;
    }
    __syncthreads();
    int c = cb + cg * 2;
    float2 v0 = upk(acc0);
    float2 v1 = upk(acc1);
    *(float2*)&outp[(size_t)(tr * 2) * Nout + c]     = v0;
    *(float2*)&outp[(size_t)(tr * 2 + 1) * Nout + c] = v1;
}

// ---------------- LSTM reduce unit (8 split-K partials) --------------------
__device__ __forceinline__ void lstm_reduce_unit(
    int gid, const float* bias, int use_xadd, int t, int store_enc)
{
    int base = gid * 4;
    int b = base >> 10, d = base & 1023;
    const float4* xadd = (const float4*)(g_Xenc + (size_t)t * BB * G4);
    float4 gv[4];
#pragma unroll
    for (int g = 0; g < 4; g++) {
        int off4 = (b * G4 + g * DH + d) >> 2;
        float4 s = bias ? ((const float4*)bias)[(g * DH + d) >> 2]
                        : make_float4(0.f, 0.f, 0.f, 0.f);
        if (use_xadd) {
            float4 xv = xadd[off4];
            s.x += xv.x; s.y += xv.y; s.z += xv.z; s.w += xv.w;
        }
#pragma unroll
        for (int sp = 0; sp < 8; sp++) {
            float4 p = ((const float4*)g_part)[sp * (BB * G4 / 4) + off4];
            s.x += p.x; s.y += p.y; s.z += p.z; s.w += p.w;
        }
        gv[g] = s;
    }
    float4 cold = ((const float4*)g_c)[gid];
    float4 cn, hn;
    {
        float* iv = (float*)&gv[0]; float* fv = (float*)&gv[1];
        float* gg = (float*)&gv[2]; float* ov = (float*)&gv[3];
        float* cp = (float*)&cold; float* cnp = (float*)&cn; float* hnp = (float*)&hn;
#pragma unroll
        for (int j = 0; j < 4; j++) {
            float cc = sigm(fv[j]) * cp[j] + sigm(iv[j]) * tanhf(gg[j]);
            cnp[j] = cc;
            hnp[j] = sigm(ov[j]) * tanhf(cc);
        }
    }
    ((float4*)g_c)[gid] = cn;
    ((float4*)g_h)[gid] = hn;
    if (store_enc)
        ((float4*)g_enc_outs)[((b * LL + t) * DH + d) >> 2] = hn;
}

// merge 125 tile stats for row b; writes g_lse[b][lse_t]; returns argmax tok.
__device__ __forceinline__ int merge_row_stats(int b, int lse_t, char* SM)
{
    int tid = threadIdx.x;
    float* mm = (float*)SM;            // 128 floats
    float* ms = mm + 128;              // 128 floats
    int*   mi = (int*)(ms + 128);      // 128 ints
    float v = -3.4e38f; int ii = 0x7fffffff;
    if (tid < NTILES_OP) { v = g_pm[b][tid]; ii = g_pi[b][tid]; }
    if (tid < 128) { mm[tid] = v; mi[tid] = ii; }
    __syncthreads();
    for (int off = 64; off >= 1; off >>= 1) {
        if (tid < off) {
            float o = mm[tid + off]; int oi = mi[tid + off];
            if (o > mm[tid] || (o == mm[tid] && oi < mi[tid])) {
                mm[tid] = o; mi[tid] = oi;
            }
        }
        __syncthreads();
    }
    float M = mm[0]; int tok = mi[0];
    __syncthreads();
    float sv = 0.f;
    if (tid < NTILES_OP) sv = g_ps[b][tid] * __expf(g_pm[b][tid] - M);
    if (tid < 128) ms[tid] = sv;
    __syncthreads();
    for (int off = 64; off >= 1; off >>= 1) {
        if (tid < off) ms[tid] += ms[tid + off];
        __syncthreads();
    }
    if (tid == 0) g_lse[b][lse_t] = M + logf(ms[0]);
    __syncthreads();
    return tok;
}

// ---------------- THE persistent kernel ------------------------------------
__global__ __launch_bounds__(NT, 1) void k_persist(
    const float* __restrict__ enc_wh,
    const float* __restrict__ dec_embed, const float* __restrict__ attn_w,
    const float* __restrict__ attn_b,
    const float* __restrict__ comb_w, const float* __restrict__ comb_b,
    const float* __restrict__ dec_wx, const float* __restrict__ dec_wh,
    const float* __restrict__ dec_b,
    const float* __restrict__ out_w, const float* __restrict__ out_b,
    float* __restrict__ out)
{
    __shared__ __align__(16) char SM[41984];
    int bx = blockIdx.x, tid = threadIdx.x;
    int nb = gridDim.x;
    int nthr = nb * NT;
    int gid0 = bx * NT + tid;
    int upb = (BB * DH / 4 + nb - 1) / nb;   // reduce units per block

    // ---- init h=c=0 ----
    for (int u = gid0; u < BB * DH / 4; u += nthr) {
        ((float4*)g_h)[u] = make_float4(0.f, 0.f, 0.f, 0.f);
        ((float4*)g_c)[u] = make_float4(0.f, 0.f, 0.f, 0.f);
    }
    gsync();

    // ================= encoder: 64 steps =================
    for (int t = 0; t < LL; t++) {
        for (int u = bx; u < 128; u += nb) {      // 16 tiles x 8 splits (KC=128)
            int ct = u & 15, sp = u >> 4;
            int k0 = sp * 128;
            gemm256(g_h + k0, enc_wh + (size_t)k0 * G4, G4, 128,
                    g_part + (size_t)sp * BB * G4, G4, ct * 256, SM);
            __syncthreads();
        }
        gsync();
        if (tid < upb) {
            int u = bx * upb + tid;
            if (u < BB * DH / 4) lstm_reduce_unit(u, nullptr, 1, t, 1);
        }
        gsync();
    }

    // ---- decoder init ----
    for (int u = gid0; u < BB * DH / 4; u += nthr) {
        ((float4*)g_h)[u] = make_float4(0.f, 0.f, 0.f, 0.f);
        ((float4*)g_c)[u] = make_float4(0.f, 0.f, 0.f, 0.f);
    }
    gsync();

    // ================= decoder: 64 steps =================
    for (int t = 0; t < LL; t++) {
        // ---- P1: per-row stats merge (t>0) + attention ----
        for (int b = bx; b < BB; b += nb) {
            int tok;
            if (t == 0) tok = 127;
            else        tok = merge_row_stats(b, t - 1, SM);

            float* se  = (float*)SM;           // 1024
            float* sh  = se + DH;              // 1024
            float* sc  = sh + DH;              // 64
            float* sp8 = sc + 64;              // 8*64
            float* red = sp8 + 512;            // 128
            for (int k = tid; k < DH; k += NT) {
                float e = dec_embed[(size_t)tok * DH + k];
                se[k] = e;
                g_e[b * DH + k] = e;
                sh[k] = g_h[b * DH + k];
            }
            __syncthreads();
            int l = tid & 63, kg = tid >> 6;   // 8 K-groups of 256
            const float* src = (kg < 4) ? (se + kg * 256) : (sh + (kg - 4) * 256);
            const float* wbase = attn_w + (size_t)(kg * 256) * LL + l;
            float p0 = 0.f, p1 = 0.f, p2 = 0.f, p3 = 0.f;
            float p4 = 0.f, p5 = 0.f, p6 = 0.f, p7 = 0.f;
#pragma unroll 2
            for (int kk = 0; kk < 256; kk += 8) {
                p0 += src[kk + 0] * wbase[(size_t)(kk + 0) * LL];
                p1 += src[kk + 1] * wbase[(size_t)(kk + 1) * LL];
                p2 += src[kk + 2] * wbase[(size_t)(kk + 2) * LL];
                p3 += src[kk + 3] * wbase[(size_t)(kk + 3) * LL];
                p4 += src[kk + 4] * wbase[(size_t)(kk + 4) * LL];
                p5 += src[kk + 5] * wbase[(size_t)(kk + 5) * LL];
                p6 += src[kk + 6] * wbase[(size_t)(kk + 6) * LL];
                p7 += src[kk + 7] * wbase[(size_t)(kk + 7) * LL];
            }
            sp8[kg * 64 + l] = ((p0 + p1) + (p2 + p3)) + ((p4 + p5) + (p6 + p7));
            __syncthreads();
            if (tid < 64) {
                float s = attn_b[tid];
#pragma unroll
                for (int g = 0; g < 8; g++) s += sp8[g * 64 + tid];
                sc[tid] = s;
            }
            __syncthreads();
            if (tid < 64) red[tid] = sc[tid];
            __syncthreads();
            for (int off = 32; off >= 1; off >>= 1) {
                if (tid < off) red[tid] = fmaxf(red[tid], red[tid + off]);
                __syncthreads();
            }
            float mx = red[0];
            __syncthreads();
            if (tid < 64) { float e = expf(sc[tid] - mx); sc[tid] = e; red[tid] = e; }
            __syncthreads();
            for (int off = 32; off >= 1; off >>= 1) {
                if (tid < off) red[tid] += red[tid + off];
                __syncthreads();
            }
            float inv = 1.f / red[0];
            __syncthreads();
            if (tid < 64) sc[tid] *= inv;
            __syncthreads();
            if (tid < 256) {
                float4 acc4 = make_float4(0.f, 0.f, 0.f, 0.f);
                const float4* eob = (const float4*)(g_enc_outs + (size_t)b * LL * DH);
#pragma unroll 4
                for (int l2 = 0; l2 < LL; l2++) {
                    float a = sc[l2];
                    float4 e4 = eob[l2 * 256 + tid];
                    acc4.x += a * e4.x; acc4.y += a * e4.y;
                    acc4.z += a * e4.z; acc4.w += a * e4.w;
                }
                ((float4*)(g_ctx + b * DH))[tid] = acc4;
            }
            __syncthreads();
        }
        gsync();

        // ---- P2: comb gemm (16 tiles x 8 splits, KC=256) -> g_part2 ----
        for (int u = bx; u < 128; u += nb) {
            int ct = u & 15, sp = u >> 4;
            int k0 = sp * 256;
            const float* Ab = (k0 < DH) ? (g_e + k0) : (g_ctx + k0 - DH);
            gemm64(Ab, comb_w + (size_t)k0 * DH, DH, 256,
                   g_part2 + (size_t)sp * BB * DH, DH, ct * 64, SM);
            __syncthreads();
        }
        gsync();

        // ---- P4: gates gemm (16 tiles x 8 splits over K=2048, KC=256);
        //          comb reduce+relu fused into the A-loader for k0 < DH ----
        for (int u = bx; u < 128; u += nb) {
            int ct = u & 15, sp = u >> 4;
            int k0 = sp * 256;
            if (k0 < DH) {
                gemm256_comb(k0, comb_b, dec_wx + (size_t)k0 * G4, G4, 256,
                             g_part + (size_t)sp * BB * G4, G4, ct * 256, SM);
            } else {
                gemm256(g_h + (k0 - DH), dec_wh + (size_t)(k0 - DH) * G4, G4, 256,
                        g_part + (size_t)sp * BB * G4, G4, ct * 256, SM);
            }
            __syncthreads();
        }
        gsync();

        // ---- P5: LSTM reduce (all blocks, contiguous per-block units) ----
        if (tid < upb) {
            int u = bx * upb + tid;
            if (u < BB * DH / 4) lstm_reduce_unit(u, dec_b, 0, t, 0);
        }
        gsync();

        // ---- P6: output projection + fused per-tile softmax stats ----
        for (int u = bx; u < NTILES_OP; u += nb) {
            outproj256(g_h, out_w, VV, DH, out_b, out, t, u, u * 256, SM);
            __syncthreads();
        }
        gsync();
    }

    // ================= epilogue =================
    for (int b = bx; b < BB; b += nb)
        (void)merge_row_stats(b, LL - 1, SM);
    gsync();

    {
        const int TOT4 = BB * LL * (VV / 4);
        const float* lsef = &g_lse[0][0];
        float4* out4 = (float4*)out;
        for (int i = gid0; i < TOT4; i += nthr) {
            int r = i / (VV / 4);
            float l = lsef[r];
            float4 v = out4[i];
            v.x -= l; v.y -= l; v.z -= l; v.w -= l;
            out4[i] = v;
        }
    }
}

// ---------------- host launcher --------------------------------------------
extern "C" void kernel_launch(void* const* d_in, const int* in_sizes, int n_in,
                              void* d_out, int out_size)
{
    (void)in_sizes; (void)n_in; (void)out_size;
    const int*   x         = (const int*)  d_in[0];
    const float* enc_embed = (const float*)d_in[1];
    const float* enc_wx    = (const float*)d_in[2];
    const float* enc_wh    = (const float*)d_in[3];
    const float* enc_b     = (const float*)d_in[4];
    const float* dec_embed = (const float*)d_in[5];
    const float* attn_w    = (const float*)d_in[6];
    const float* attn_b    = (const float*)d_in[7];
    const float* comb_w    = (const float*)d_in[8];
    const float* comb_b    = (const float*)d_in[9];
    const float* dec_wx    = (const float*)d_in[10];
    const float* dec_wh    = (const float*)d_in[11];
    const float* dec_b     = (const float*)d_in[12];
    const float* out_w     = (const float*)d_in[13];
    const float* out_b     = (const float*)d_in[14];
    float* out = (float*)d_out;

    int dev = 0, nsm = MAXBLK;
    cudaGetDevice(&dev);
    cudaDeviceGetAttribute(&nsm, cudaDevAttrMultiProcessorCount, dev);
    int nblk = nsm < MAXBLK ? nsm : MAXBLK;

    k_enc_pre<<<dim3(32, 1, 64), 256>>>(x, enc_embed, enc_wx, enc_b);
    k_persist<<<nblk, NT>>>(enc_wh, dec_embed, attn_w, attn_b,
                            comb_w, comb_b, dec_wx, dec_wh, dec_b,
                            out_w, out_b, out);
}